// round 10
// baseline (speedup 1.0000x reference)
#include <cuda_runtime.h>
#include <cuda_fp16.h>
#include <math.h>
#include <stdint.h>

#define NLAYERS 4
#define DM      64
#define DS      128
#define DCONV   4
#define DI      128
#define NH      2
#define HD      64
#define CONVD   384
#define DZX     512
#define BSZ     8
#define SEQ     4096
#define BL      (BSZ*SEQ)
#define QC      64
#define NC      (SEQ/QC)
#define EPSV    1e-5f

__device__ float  g_z   [BL*(long)DI];         /* z columns, fp32          */
__device__ __half g_xbch[BL*(long)CONVD];      /* xBC columns, fp16        */
__device__ float  g_c   [BL*(long)DS];         /* post-conv C, fp32        */
__device__ float  g_lacc[BSZ*NH*SEQ];
__device__ float  g_atot[BSZ*NH*NC];
__device__ float  g_S   [(long)BSZ*NH*NC*HD*DS];
__device__ float  g_hst [(long)BSZ*NH*NC*HD*DS];
__device__ float  g_y   [BL*(long)DI];

__device__ __forceinline__ float siluf(float v){ return v / (1.f + __expf(-v)); }

__device__ __forceinline__ float4 ldh4(const __half* p){
    __half2 a = *(const __half2*)p;
    __half2 b = *(const __half2*)(p+2);
    float2 fa = __half22float2(a);
    float2 fb = __half22float2(b);
    return make_float4(fa.x, fa.y, fb.x, fb.y);
}

__device__ __forceinline__ void mma8(float* d, uint32_t a0, uint32_t a1, uint32_t a2, uint32_t a3,
                                     uint32_t b0, uint32_t b1){
    asm volatile("mma.sync.aligned.m16n8k8.row.col.f32.tf32.tf32.f32 "
                 "{%0,%1,%2,%3}, {%4,%5,%6,%7}, {%8,%9}, {%0,%1,%2,%3};\n"
                 : "+f"(d[0]), "+f"(d[1]), "+f"(d[2]), "+f"(d[3])
                 : "r"(a0), "r"(a1), "r"(a2), "r"(a3), "r"(b0), "r"(b1));
}
#define F2U(v) __float_as_uint(v)

__global__ void copy_kernel(const float* __restrict__ src, float* __restrict__ dst, int n4){
    int i = blockIdx.x*blockDim.x + threadIdx.x;
    if (i < n4) ((float4*)dst)[i] = ((const float4*)src)[i];
}

/* ---- in_proj GEMM (tf32 mma): z tile -> g_z fp32, xBC tiles -> g_xbch fp16 */
__global__ void inproj_kernel(const float* __restrict__ x, const float* __restrict__ W){
    __shared__ float As[128*68];    /* [m][k] */
    __shared__ float Bs[64*136];    /* [k][n] */
    int m0 = blockIdx.x*128, n0 = blockIdx.y*128, tid = threadIdx.x;
    for (int idx = tid; idx < 128*16; idx += 256){
        int m = idx >> 4, k4 = idx & 15;
        *(float4*)&As[m*68 + k4*4] = *(const float4*)&x[(long)(m0+m)*DM + k4*4];
    }
    for (int idx = tid; idx < 128*16; idx += 256){
        int n = idx >> 4, k4 = (idx & 15)*4;
        float4 wv = *(const float4*)&W[(long)(n0+n)*DM + k4];
        Bs[(k4+0)*136 + n] = wv.x;
        Bs[(k4+1)*136 + n] = wv.y;
        Bs[(k4+2)*136 + n] = wv.z;
        Bs[(k4+3)*136 + n] = wv.w;
    }
    __syncthreads();
    int w = tid >> 5, lane = tid & 31, gr = lane >> 2, tg = lane & 3;
    float acc[16][4];
    #pragma unroll
    for (int j=0;j<16;j++){ acc[j][0]=acc[j][1]=acc[j][2]=acc[j][3]=0.f; }
    const float* Ar0 = &As[(w*16+gr)*68];
    const float* Ar1 = Ar0 + 8*68;
    #pragma unroll
    for (int k0 = 0; k0 < 64; k0 += 8){
        uint32_t a0 = F2U(Ar0[k0+tg]),   a1 = F2U(Ar1[k0+tg]);
        uint32_t a2 = F2U(Ar0[k0+tg+4]), a3 = F2U(Ar1[k0+tg+4]);
        const float* Bk0 = &Bs[(k0+tg)*136 + gr];
        const float* Bk1 = Bk0 + 4*136;
        #pragma unroll
        for (int j=0;j<16;j++)
            mma8(acc[j], a0,a1,a2,a3, F2U(Bk0[j*8]), F2U(Bk1[j*8]));
    }
    long row0 = m0 + w*16 + gr;
    if (n0 == 0){
        #pragma unroll
        for (int j=0;j<16;j++){
            int col = j*8 + 2*tg;
            *(float2*)&g_z[row0*DI + col]     = make_float2(acc[j][0], acc[j][1]);
            *(float2*)&g_z[(row0+8)*DI + col] = make_float2(acc[j][2], acc[j][3]);
        }
    } else {
        int cb = n0 - DI;
        #pragma unroll
        for (int j=0;j<16;j++){
            int col = cb + j*8 + 2*tg;
            *(__half2*)&g_xbch[row0*CONVD + col]     = __floats2half2_rn(acc[j][0], acc[j][1]);
            *(__half2*)&g_xbch[(row0+8)*CONVD + col] = __floats2half2_rn(acc[j][2], acc[j][3]);
        }
    }
}

/* -------- Phase A: dt scan, conv+SiLU (vec4), G/W/Y/S via tf32 mma --------- */
#define SMA_FLOATS (64*132 + 128*68 + 64*136 + 3*128)
__global__ void phaseA_kernel(const float* __restrict__ x, const float* __restrict__ W,
                              const float* __restrict__ dtb, const float* __restrict__ alog,
                              const float* __restrict__ cw, const float* __restrict__ cb,
                              const float* __restrict__ Dp){
    int b = blockIdx.x >> 6;
    int c = blockIdx.x & (NC-1);
    int l0 = c*QC;
    extern __shared__ float sm[];
    float* Cs   = sm;                   /* C [t][s] s132; later Ws [t][h*64+tp] */
    float* R0   = sm + 64*132;          /* B^T [s][t] s68 */
    float* Xs   = R0 + 128*68;          /* X [t][pg] s136 */
    float* la_s = Xs + 64*136;          /* [h*64+t] */
    float* dt_s = la_s + 128;
    float* cf_s = dt_s + 128;
    int tid = threadIdx.x;

    if (tid < NH*QC){
        int h = tid >> 6, t = tid & 63;
        const float* xr = x + ((long)(b*SEQ + l0 + t))*DM;
        const float* wr = W + (long)(DZX+h)*DM;
        float raw = __ldg(&dtb[h]);
        #pragma unroll
        for (int k4 = 0; k4 < 16; k4++){
            float4 wv = *(const float4*)&wr[k4*4];
            float4 a  = *(const float4*)&xr[k4*4];
            raw = fmaf(a.x,wv.x, fmaf(a.y,wv.y, fmaf(a.z,wv.z, fmaf(a.w,wv.w, raw))));
        }
        dt_s[tid] = (raw > 20.f) ? raw : log1pf(__expf(raw));
    }

    for (int idx = tid; idx < QC*(CONVD/4); idx += 256){
        int t   = idx / (CONVD/4);
        int c4g = idx - t*(CONVD/4);
        int ch  = c4g*4;
        int l   = l0 + t;
        long rowb = (long)(b*SEQ + l);
        float4 v0 = make_float4(0.f,0.f,0.f,0.f), v1 = v0, v2 = v0, v3 = v0;
        {
            int ll;
            ll = l-3; if (ll>=0) v0 = ldh4(&g_xbch[((long)(b*SEQ+ll))*CONVD + ch]);
            ll = l-2; if (ll>=0) v1 = ldh4(&g_xbch[((long)(b*SEQ+ll))*CONVD + ch]);
            ll = l-1; if (ll>=0) v2 = ldh4(&g_xbch[((long)(b*SEQ+ll))*CONVD + ch]);
            v3 = ldh4(&g_xbch[rowb*CONVD + ch]);
        }
        float4 bias = *(const float4*)&cb[ch];
        float4 w0 = *(const float4*)&cw[ch*4];
        float4 w1 = *(const float4*)&cw[ch*4+4];
        float4 w2 = *(const float4*)&cw[ch*4+8];
        float4 w3 = *(const float4*)&cw[ch*4+12];
        float o0 = siluf(bias.x + w0.x*v0.x + w0.y*v1.x + w0.z*v2.x + w0.w*v3.x);
        float o1 = siluf(bias.y + w1.x*v0.y + w1.y*v1.y + w1.z*v2.y + w1.w*v3.y);
        float o2 = siluf(bias.z + w2.x*v0.z + w2.y*v1.z + w2.z*v2.z + w2.w*v3.z);
        float o3 = siluf(bias.w + w3.x*v0.w + w3.y*v1.w + w3.z*v2.w + w3.w*v3.w);
        float4 ov = make_float4(o0,o1,o2,o3);
        if (ch < DI){
            *(float4*)&Xs[t*136 + ch] = ov;
        } else if (ch < DI+DS){
            int s = ch - DI;
            R0[(s+0)*68 + t] = o0;
            R0[(s+1)*68 + t] = o1;
            R0[(s+2)*68 + t] = o2;
            R0[(s+3)*68 + t] = o3;
        } else {
            int s = ch - DI - DS;
            *(float4*)&Cs[t*132 + s] = ov;
            *(float4*)&g_c[rowb*DS + s] = ov;
        }
    }
    __syncthreads();

    int w = tid >> 5, lane = tid & 31, gr = lane >> 2, tg = lane & 3;
    if (w < NH){
        int h = w;
        float Aneg = -__expf(__ldg(&alog[h]));
        float dt0 = dt_s[h*64 + 2*lane];
        float dt1 = dt_s[h*64 + 2*lane + 1];
        float pp = (dt0 + dt1) * Aneg;
        float s = pp;
        #pragma unroll
        for (int o=1;o<32;o<<=1){ float v = __shfl_up_sync(0xffffffffu, s, o); if (lane >= o) s += v; }
        float la1 = s;
        float la0 = s - pp + dt0*Aneg;
        float at  = __shfl_sync(0xffffffffu, s, 31);
        la_s[h*64 + 2*lane]     = la0;
        la_s[h*64 + 2*lane + 1] = la1;
        cf_s[h*64 + 2*lane]     = __expf(at - la0) * dt0;
        cf_s[h*64 + 2*lane + 1] = __expf(at - la1) * dt1;
        long gbase = ((long)(b*NH + h))*SEQ + l0 + 2*lane;
        g_lacc[gbase]   = la0;
        g_lacc[gbase+1] = la1;
        if (lane == 31) g_atot[(b*NH+h)*NC + c] = at;
    }

    int mt = w & 3;
    int t0 = mt*16;
    int ntb = (w >> 2)*4;
    int h = w >> 2;

    float gfr[4][4];
    #pragma unroll
    for (int j=0;j<4;j++){ gfr[j][0]=gfr[j][1]=gfr[j][2]=gfr[j][3]=0.f; }
    {
        const float* Ar0 = &Cs[(t0+gr)*132];
        const float* Ar1 = Ar0 + 8*132;
        #pragma unroll
        for (int k0 = 0; k0 < 128; k0 += 8){
            uint32_t a0 = F2U(Ar0[k0+tg]),   a1 = F2U(Ar1[k0+tg]);
            uint32_t a2 = F2U(Ar0[k0+tg+4]), a3 = F2U(Ar1[k0+tg+4]);
            const float* Bk0 = &R0[(k0+tg)*68 + ntb*8 + gr];
            const float* Bk1 = Bk0 + 4*68;
            #pragma unroll
            for (int j=0;j<4;j++)
                mma8(gfr[j], a0,a1,a2,a3, F2U(Bk0[j*8]), F2U(Bk1[j*8]));
        }
    }
    __syncthreads();

    #pragma unroll
    for (int hh=0; hh<NH; hh++){
        float laT0 = la_s[hh*64 + t0+gr];
        float laT1 = la_s[hh*64 + t0+gr+8];
        #pragma unroll
        for (int j=0;j<4;j++){
            int tp0 = (ntb+j)*8 + 2*tg;
            float dtp0 = dt_s[hh*64 + tp0],  dtp1 = dt_s[hh*64 + tp0+1];
            float lap0 = la_s[hh*64 + tp0],  lap1 = la_s[hh*64 + tp0+1];
            int tA = t0+gr, tB = t0+gr+8;
            float w00 = (tp0   <= tA) ? __expf(laT0-lap0)*dtp0*gfr[j][0] : 0.f;
            float w01 = (tp0+1 <= tA) ? __expf(laT0-lap1)*dtp1*gfr[j][1] : 0.f;
            float w10 = (tp0   <= tB) ? __expf(laT1-lap0)*dtp0*gfr[j][2] : 0.f;
            float w11 = (tp0+1 <= tB) ? __expf(laT1-lap1)*dtp1*gfr[j][3] : 0.f;
            Cs[tA*132 + hh*64 + tp0]   = w00;
            Cs[tA*132 + hh*64 + tp0+1] = w01;
            Cs[tB*132 + hh*64 + tp0]   = w10;
            Cs[tB*132 + hh*64 + tp0+1] = w11;
        }
    }
    __syncthreads();

    /* Y GEMM + D*x skip folded in */
    {
        float ya[8][4];
        #pragma unroll
        for (int j=0;j<8;j++){ ya[j][0]=ya[j][1]=ya[j][2]=ya[j][3]=0.f; }
        const float* Wr0 = &Cs[(t0+gr)*132 + h*64];
        const float* Wr1 = Wr0 + 8*132;
        #pragma unroll
        for (int k0 = 0; k0 < 64; k0 += 8){
            uint32_t a0 = F2U(Wr0[k0+tg]),   a1 = F2U(Wr1[k0+tg]);
            uint32_t a2 = F2U(Wr0[k0+tg+4]), a3 = F2U(Wr1[k0+tg+4]);
            const float* Bk0 = &Xs[(k0+tg)*136 + h*64 + gr];
            const float* Bk1 = Bk0 + 4*136;
            #pragma unroll
            for (int j=0;j<8;j++)
                mma8(ya[j], a0,a1,a2,a3, F2U(Bk0[j*8]), F2U(Bk1[j*8]));
        }
        float dh = __ldg(&Dp[h]);
        long row0 = (long)(b*SEQ + l0 + t0 + gr);
        #pragma unroll
        for (int j=0;j<8;j++){
            int col = h*64 + j*8 + 2*tg;
            float2 xa = *(const float2*)&Xs[(t0+gr)*136 + col];
            float2 xb = *(const float2*)&Xs[(t0+gr+8)*136 + col];
            *(float2*)&g_y[row0*DI + col] =
                make_float2(ya[j][0] + dh*xa.x, ya[j][1] + dh*xa.y);
            *(float2*)&g_y[(row0+8)*DI + col] =
                make_float2(ya[j][2] + dh*xb.x, ya[j][3] + dh*xb.y);
        }
    }

    {
        float sa[16][4];
        #pragma unroll
        for (int j=0;j<16;j++){ sa[j][0]=sa[j][1]=sa[j][2]=sa[j][3]=0.f; }
        int pg0 = w*16;
        #pragma unroll
        for (int k0 = 0; k0 < 64; k0 += 8){
            float cfA = cf_s[h*64 + k0+tg];
            float cfB = cf_s[h*64 + k0+tg+4];
            const float* Xk0 = &Xs[(k0+tg)*136 + pg0 + gr];
            const float* Xk1 = Xk0 + 4*136;
            uint32_t a0 = F2U(Xk0[0]*cfA), a1 = F2U(Xk0[8]*cfA);
            uint32_t a2 = F2U(Xk1[0]*cfB), a3 = F2U(Xk1[8]*cfB);
            #pragma unroll
            for (int j=0;j<16;j++){
                const float* Bp = &R0[(j*8+gr)*68 + k0+tg];
                mma8(sa[j], a0,a1,a2,a3, F2U(Bp[0]), F2U(Bp[4]));
            }
        }
        int p = (w&3)*16 + gr;
        long base = (((long)((b*NH+h)*NC + c))*HD)*DS;
        #pragma unroll
        for (int j=0;j<16;j++){
            int s = j*8 + 2*tg;
            *(float2*)&g_S[base + (long)p*DS + s]     = make_float2(sa[j][0], sa[j][1]);
            *(float2*)&g_S[base + (long)(p+8)*DS + s] = make_float2(sa[j][2], sa[j][3]);
        }
    }
}

/* ------ Phase B: inter-chunk recurrence, depth-8 ring, contiguous layout --- */
__global__ void phaseB_kernel(void){
    __shared__ float ea_s[NC];
    int bh   = blockIdx.x >> 4;
    int part = blockIdx.x & 15;
    int tid  = threadIdx.x;           /* 128 threads */
    if (tid < NC) ea_s[tid] = __expf(g_atot[bh*NC + tid]);
    __syncthreads();
    long ebase = (long)bh*NC*(HD*DS) + part*512 + tid*4;
    float4 hv = make_float4(0.f,0.f,0.f,0.f);
    float4 ring[8];
    #pragma unroll
    for (int d=0;d<8;d++) ring[d] = *(const float4*)&g_S[ebase + (long)d*(HD*DS)];
    for (int c = 0; c < NC; c++){
        *(float4*)&g_hst[ebase + (long)c*(HD*DS)] = hv;
        float ea = ea_s[c];
        float4 sv = ring[c & 7];
        hv.x = fmaf(hv.x, ea, sv.x);
        hv.y = fmaf(hv.y, ea, sv.y);
        hv.z = fmaf(hv.z, ea, sv.z);
        hv.w = fmaf(hv.w, ea, sv.w);
        if (c + 8 < NC)
            ring[c & 7] = *(const float4*)&g_S[ebase + (long)(c+8)*(HD*DS)];
    }
}

/* ------ Phase C+G (tf32 mma): inter-chunk out, gate, RMSNorm, out_proj ----- */
#define SMCG_FLOATS (64*132 + 128*136 + 128)
__global__ void phaseCG_kernel(const float* __restrict__ ow,
                               const float* __restrict__ nw, float* __restrict__ xres){
    int b = blockIdx.x >> 6;
    int c = blockIdx.x & (NC-1);
    int l0 = c*QC;
    extern __shared__ float sm[];
    float* Cs2 = sm;
    float* Hs  = sm + 64*132;
    float* yt  = Hs;
    float* owT = Cs2;
    float* la2 = sm + 64*132 + 128*136;
    int tid = threadIdx.x;

    for (int idx = tid; idx < QC*(DS/4); idx += 256){
        int t = idx >> 5, s4 = (idx & 31)*4;
        *(float4*)&Cs2[t*132 + s4] =
            *(const float4*)&g_c[((long)(b*SEQ+l0+t))*DS + s4];
    }
    for (int idx = tid; idx < DS*NH*HD; idx += 256){
        int s = idx & 127, pg = idx >> 7;
        Hs[s*136 + pg] = g_hst[(((long)((b*NH+(pg>>6))*NC + c))*HD + (pg&63))*DS + s];
    }
    if (tid < NH*QC){
        int hh = tid >> 6, t = tid & 63;
        la2[tid] = g_lacc[((long)(b*NH+hh))*SEQ + l0 + t];
    }
    __syncthreads();

    int w = tid >> 5, lane = tid & 31, gr = lane >> 2, tg = lane & 3;
    int mt = w & 3, t0 = mt*16, h = w >> 2;
    long row0 = (long)(b*SEQ + l0 + t0 + gr);
    long row1 = row0 + 8;

    float acc[8][4];
    #pragma unroll
    for (int j=0;j<8;j++){ acc[j][0]=acc[j][1]=acc[j][2]=acc[j][3]=0.f; }
    {
        const float* Ar0 = &Cs2[(t0+gr)*132];
        const float* Ar1 = Ar0 + 8*132;
        #pragma unroll
        for (int k0 = 0; k0 < 128; k0 += 8){
            uint32_t a0 = F2U(Ar0[k0+tg]),   a1 = F2U(Ar1[k0+tg]);
            uint32_t a2 = F2U(Ar0[k0+tg+4]), a3 = F2U(Ar1[k0+tg+4]);
            const float* Bk0 = &Hs[(k0+tg)*136 + h*64 + gr];
            const float* Bk1 = Bk0 + 4*136;
            #pragma unroll
            for (int j=0;j<8;j++)
                mma8(acc[j], a0,a1,a2,a3, F2U(Bk0[j*8]), F2U(Bk1[j*8]));
        }
    }
    float e0 = __expf(la2[h*64 + t0+gr]);
    float e1 = __expf(la2[h*64 + t0+gr+8]);
    float gated[8][4];
    #pragma unroll
    for (int j=0;j<8;j++){
        int col = h*64 + j*8 + 2*tg;
        float2 y0 = *(const float2*)&g_y[row0*DI + col];
        float2 z0 = *(const float2*)&g_z[row0*DI + col];
        float2 y1 = *(const float2*)&g_y[row1*DI + col];
        float2 z1 = *(const float2*)&g_z[row1*DI + col];
        gated[j][0] = (y0.x + e0*acc[j][0]) * siluf(z0.x);
        gated[j][1] = (y0.y + e0*acc[j][1]) * siluf(z0.y);
        gated[j][2] = (y1.x + e1*acc[j][2]) * siluf(z1.x);
        gated[j][3] = (y1.y + e1*acc[j][3]) * siluf(z1.y);
    }
    __syncthreads();

    #pragma unroll
    for (int j=0;j<8;j++){
        int col = h*64 + j*8 + 2*tg;
        *(float2*)&yt[(t0+gr)*136   + col] = make_float2(gated[j][0], gated[j][1]);
        *(float2*)&yt[(t0+gr+8)*136 + col] = make_float2(gated[j][2], gated[j][3]);
    }
    for (int idx = tid; idx < DM*DI; idx += 256){
        int m = idx >> 7, k = idx & 127;
        owT[k*66 + m] = ow[idx];
    }
    __syncthreads();

    for (int r = w*8; r < w*8 + 8; r++){
        float s = 0.f;
        #pragma unroll
        for (int q=0;q<4;q++){ float v = yt[r*136 + lane + q*32]; s += v*v; }
        #pragma unroll
        for (int o=16;o;o>>=1) s += __shfl_xor_sync(0xffffffffu, s, o);
        float rstd = rsqrtf(s/(float)DI + EPSV);
        #pragma unroll
        for (int q=0;q<4;q++){
            int cc = lane + q*32;
            yt[r*136 + cc] *= rstd * __ldg(&nw[cc]);
        }
    }
    __syncthreads();

    {
        float oacc[4][4];
        #pragma unroll
        for (int j=0;j<4;j++){ oacc[j][0]=oacc[j][1]=oacc[j][2]=oacc[j][3]=0.f; }
        int ntb = (w >> 2)*4;
        const float* Ar0 = &yt[(t0+gr)*136];
        const float* Ar1 = Ar0 + 8*136;
        #pragma unroll
        for (int k0 = 0; k0 < 128; k0 += 8){
            uint32_t a0 = F2U(Ar0[k0+tg]),   a1 = F2U(Ar1[k0+tg]);
            uint32_t a2 = F2U(Ar0[k0+tg+4]), a3 = F2U(Ar1[k0+tg+4]);
            const float* Bk0 = &owT[(k0+tg)*66 + ntb*8 + gr];
            const float* Bk1 = Bk0 + 4*66;
            #pragma unroll
            for (int j=0;j<4;j++)
                mma8(oacc[j], a0,a1,a2,a3, F2U(Bk0[j*8]), F2U(Bk1[j*8]));
        }
        #pragma unroll
        for (int j=0;j<4;j++){
            int col = (ntb+j)*8 + 2*tg;
            float2 o0 = *(float2*)&xres[row0*DM + col];
            o0.x += oacc[j][0]; o0.y += oacc[j][1];
            *(float2*)&xres[row0*DM + col] = o0;
            float2 o1 = *(float2*)&xres[row1*DM + col];
            o1.x += oacc[j][2]; o1.y += oacc[j][3];
            *(float2*)&xres[row1*DM + col] = o1;
        }
    }
}

/* ---------------- host ----------------------------------------------------- */
extern "C" void kernel_launch(void* const* d_in, const int* in_sizes, int n_in,
                              void* d_out, int out_size){
    const float* x0    = (const float*)d_in[0];
    const float* inw   = (const float*)d_in[1];
    const float* cw    = (const float*)d_in[2];
    const float* cb    = (const float*)d_in[3];
    const float* dtb   = (const float*)d_in[4];
    const float* alog  = (const float*)d_in[5];
    const float* Dpar  = (const float*)d_in[6];
    const float* nw    = (const float*)d_in[7];
    const float* ow    = (const float*)d_in[8];
    float* out = (float*)d_out;

    cudaFuncSetAttribute(phaseA_kernel,  cudaFuncAttributeMaxDynamicSharedMemorySize, SMA_FLOATS*4);
    cudaFuncSetAttribute(phaseCG_kernel, cudaFuncAttributeMaxDynamicSharedMemorySize, SMCG_FLOATS*4);

    copy_kernel<<<(BL*DM/4+255)/256, 256>>>(x0, out, BL*DM/4);

    const int DPROJ = DZX + NH;
    for (int layer = 0; layer < NLAYERS; layer++){
        const float* Wl = inw + (long)layer*DPROJ*DM;
        inproj_kernel<<<dim3(BL/128, DZX/128), 256>>>(out, Wl);
        phaseA_kernel<<<BSZ*NC, 256, SMA_FLOATS*4>>>(out, Wl, dtb + layer*NH, alog + layer*NH,
                                                     cw + (long)layer*CONVD*DCONV,
                                                     cb + layer*CONVD,
                                                     Dpar + layer*NH);
        phaseB_kernel<<<BSZ*NH*16, 128>>>();
        phaseCG_kernel<<<BSZ*NC, 256, SMCG_FLOATS*4>>>(ow + (long)layer*DM*DI,
                                                       nw + layer*DI, out);
    }
    (void)in_sizes; (void)n_in; (void)out_size;
}

// round 12
// speedup vs baseline: 1.0399x; 1.0399x over previous
#include <cuda_runtime.h>
#include <cuda_fp16.h>
#include <math.h>
#include <stdint.h>

#define NLAYERS 4
#define DM      64
#define DS      128
#define DCONV   4
#define DI      128
#define NH      2
#define HD      64
#define CONVD   384
#define DZX     512
#define BSZ     8
#define SEQ     4096
#define BL      (BSZ*SEQ)
#define QC      64
#define NC      (SEQ/QC)
#define EPSV    1e-5f

__device__ float  g_z   [BL*(long)DI];         /* z columns, fp32          */
__device__ __half g_xbch[BL*(long)CONVD];      /* xBC columns, fp16        */
__device__ float  g_c   [BL*(long)DS];         /* post-conv C, fp32        */
__device__ float  g_lacc[BSZ*NH*SEQ];
__device__ float  g_atot[BSZ*NH*NC];
__device__ float  g_S   [(long)BSZ*NH*NC*HD*DS];
__device__ float  g_hst [(long)BSZ*NH*NC*HD*DS];
__device__ float  g_y   [BL*(long)DI];

__device__ __forceinline__ float siluf(float v){ return v / (1.f + __expf(-v)); }

__device__ __forceinline__ float4 ldh4(const __half* p){
    __half2 a = *(const __half2*)p;
    __half2 b = *(const __half2*)(p+2);
    float2 fa = __half22float2(a);
    float2 fb = __half22float2(b);
    return make_float4(fa.x, fa.y, fb.x, fb.y);
}

__device__ __forceinline__ void mma8(float* d, uint32_t a0, uint32_t a1, uint32_t a2, uint32_t a3,
                                     uint32_t b0, uint32_t b1){
    asm volatile("mma.sync.aligned.m16n8k8.row.col.f32.tf32.tf32.f32 "
                 "{%0,%1,%2,%3}, {%4,%5,%6,%7}, {%8,%9}, {%0,%1,%2,%3};\n"
                 : "+f"(d[0]), "+f"(d[1]), "+f"(d[2]), "+f"(d[3])
                 : "r"(a0), "r"(a1), "r"(a2), "r"(a3), "r"(b0), "r"(b1));
}
#define F2U(v) __float_as_uint(v)

__global__ void copy_kernel(const float* __restrict__ src, float* __restrict__ dst, int n4){
    int i = blockIdx.x*blockDim.x + threadIdx.x;
    if (i < n4) ((float4*)dst)[i] = ((const float4*)src)[i];
}

/* ---- in_proj GEMM (tf32 mma): z tile -> g_z fp32, xBC tiles -> g_xbch fp16 */
__global__ void inproj_kernel(const float* __restrict__ x, const float* __restrict__ W){
    __shared__ float As[128*68];    /* [m][k] */
    __shared__ float Bs[64*136];    /* [k][n] */
    int m0 = blockIdx.x*128, n0 = blockIdx.y*128, tid = threadIdx.x;
    for (int idx = tid; idx < 128*16; idx += 256){
        int m = idx >> 4, k4 = idx & 15;
        *(float4*)&As[m*68 + k4*4] = *(const float4*)&x[(long)(m0+m)*DM + k4*4];
    }
    for (int idx = tid; idx < 128*16; idx += 256){
        int n = idx >> 4, k4 = (idx & 15)*4;
        float4 wv = *(const float4*)&W[(long)(n0+n)*DM + k4];
        Bs[(k4+0)*136 + n] = wv.x;
        Bs[(k4+1)*136 + n] = wv.y;
        Bs[(k4+2)*136 + n] = wv.z;
        Bs[(k4+3)*136 + n] = wv.w;
    }
    __syncthreads();
    int w = tid >> 5, lane = tid & 31, gr = lane >> 2, tg = lane & 3;
    float acc[16][4];
    #pragma unroll
    for (int j=0;j<16;j++){ acc[j][0]=acc[j][1]=acc[j][2]=acc[j][3]=0.f; }
    const float* Ar0 = &As[(w*16+gr)*68];
    const float* Ar1 = Ar0 + 8*68;
    #pragma unroll
    for (int k0 = 0; k0 < 64; k0 += 8){
        uint32_t a0 = F2U(Ar0[k0+tg]),   a1 = F2U(Ar1[k0+tg]);
        uint32_t a2 = F2U(Ar0[k0+tg+4]), a3 = F2U(Ar1[k0+tg+4]);
        const float* Bk0 = &Bs[(k0+tg)*136 + gr];
        const float* Bk1 = Bk0 + 4*136;
        #pragma unroll
        for (int j=0;j<16;j++)
            mma8(acc[j], a0,a1,a2,a3, F2U(Bk0[j*8]), F2U(Bk1[j*8]));
    }
    long row0 = m0 + w*16 + gr;
    if (n0 == 0){
        #pragma unroll
        for (int j=0;j<16;j++){
            int col = j*8 + 2*tg;
            *(float2*)&g_z[row0*DI + col]     = make_float2(acc[j][0], acc[j][1]);
            *(float2*)&g_z[(row0+8)*DI + col] = make_float2(acc[j][2], acc[j][3]);
        }
    } else {
        int cb = n0 - DI;
        #pragma unroll
        for (int j=0;j<16;j++){
            int col = cb + j*8 + 2*tg;
            *(__half2*)&g_xbch[row0*CONVD + col]     = __floats2half2_rn(acc[j][0], acc[j][1]);
            *(__half2*)&g_xbch[(row0+8)*CONVD + col] = __floats2half2_rn(acc[j][2], acc[j][3]);
        }
    }
}

/* -------- Phase A: dt scan, conv+SiLU (vec4), G/W/Y/S via tf32 mma --------- */
#define SMA_FLOATS (64*132 + 128*68 + 64*136 + 3*128)
__global__ void phaseA_kernel(const float* __restrict__ x, const float* __restrict__ W,
                              const float* __restrict__ dtb, const float* __restrict__ alog,
                              const float* __restrict__ cw, const float* __restrict__ cb,
                              const float* __restrict__ Dp){
    int b = blockIdx.x >> 6;
    int c = blockIdx.x & (NC-1);
    int l0 = c*QC;
    extern __shared__ float sm[];
    float* Cs   = sm;                   /* C [t][s] s132; later Ws [t][h*64+tp] */
    float* R0   = sm + 64*132;          /* B^T [s][t] s68 */
    float* Xs   = R0 + 128*68;          /* X [t][pg] s136 */
    float* la_s = Xs + 64*136;          /* [h*64+t] */
    float* dt_s = la_s + 128;
    float* cf_s = dt_s + 128;
    int tid = threadIdx.x;

    if (tid < NH*QC){
        int h = tid >> 6, t = tid & 63;
        const float* xr = x + ((long)(b*SEQ + l0 + t))*DM;
        const float* wr = W + (long)(DZX+h)*DM;
        float raw = __ldg(&dtb[h]);
        #pragma unroll
        for (int k4 = 0; k4 < 16; k4++){
            float4 wv = *(const float4*)&wr[k4*4];
            float4 a  = *(const float4*)&xr[k4*4];
            raw = fmaf(a.x,wv.x, fmaf(a.y,wv.y, fmaf(a.z,wv.z, fmaf(a.w,wv.w, raw))));
        }
        dt_s[tid] = (raw > 20.f) ? raw : log1pf(__expf(raw));
    }

    for (int idx = tid; idx < QC*(CONVD/4); idx += 256){
        int t   = idx / (CONVD/4);
        int c4g = idx - t*(CONVD/4);
        int ch  = c4g*4;
        int l   = l0 + t;
        long rowb = (long)(b*SEQ + l);
        float4 v0 = make_float4(0.f,0.f,0.f,0.f), v1 = v0, v2 = v0, v3 = v0;
        {
            int ll;
            ll = l-3; if (ll>=0) v0 = ldh4(&g_xbch[((long)(b*SEQ+ll))*CONVD + ch]);
            ll = l-2; if (ll>=0) v1 = ldh4(&g_xbch[((long)(b*SEQ+ll))*CONVD + ch]);
            ll = l-1; if (ll>=0) v2 = ldh4(&g_xbch[((long)(b*SEQ+ll))*CONVD + ch]);
            v3 = ldh4(&g_xbch[rowb*CONVD + ch]);
        }
        float4 bias = *(const float4*)&cb[ch];
        float4 w0 = *(const float4*)&cw[ch*4];
        float4 w1 = *(const float4*)&cw[ch*4+4];
        float4 w2 = *(const float4*)&cw[ch*4+8];
        float4 w3 = *(const float4*)&cw[ch*4+12];
        float o0 = siluf(bias.x + w0.x*v0.x + w0.y*v1.x + w0.z*v2.x + w0.w*v3.x);
        float o1 = siluf(bias.y + w1.x*v0.y + w1.y*v1.y + w1.z*v2.y + w1.w*v3.y);
        float o2 = siluf(bias.z + w2.x*v0.z + w2.y*v1.z + w2.z*v2.z + w2.w*v3.z);
        float o3 = siluf(bias.w + w3.x*v0.w + w3.y*v1.w + w3.z*v2.w + w3.w*v3.w);
        float4 ov = make_float4(o0,o1,o2,o3);
        if (ch < DI){
            *(float4*)&Xs[t*136 + ch] = ov;
        } else if (ch < DI+DS){
            int s = ch - DI;
            R0[(s+0)*68 + t] = o0;
            R0[(s+1)*68 + t] = o1;
            R0[(s+2)*68 + t] = o2;
            R0[(s+3)*68 + t] = o3;
        } else {
            int s = ch - DI - DS;
            *(float4*)&Cs[t*132 + s] = ov;
            *(float4*)&g_c[rowb*DS + s] = ov;
        }
    }
    __syncthreads();

    int w = tid >> 5, lane = tid & 31, gr = lane >> 2, tg = lane & 3;
    if (w < NH){
        int h = w;
        float Aneg = -__expf(__ldg(&alog[h]));
        float dt0 = dt_s[h*64 + 2*lane];
        float dt1 = dt_s[h*64 + 2*lane + 1];
        float pp = (dt0 + dt1) * Aneg;
        float s = pp;
        #pragma unroll
        for (int o=1;o<32;o<<=1){ float v = __shfl_up_sync(0xffffffffu, s, o); if (lane >= o) s += v; }
        float la1 = s;
        float la0 = s - pp + dt0*Aneg;
        float at  = __shfl_sync(0xffffffffu, s, 31);
        la_s[h*64 + 2*lane]     = la0;
        la_s[h*64 + 2*lane + 1] = la1;
        cf_s[h*64 + 2*lane]     = __expf(at - la0) * dt0;
        cf_s[h*64 + 2*lane + 1] = __expf(at - la1) * dt1;
        long gbase = ((long)(b*NH + h))*SEQ + l0 + 2*lane;
        g_lacc[gbase]   = la0;
        g_lacc[gbase+1] = la1;
        if (lane == 31) g_atot[(b*NH+h)*NC + c] = at;
    }

    int mt = w & 3;
    int t0 = mt*16;
    int ntb = (w >> 2)*4;
    int h = w >> 2;

    float gfr[4][4];
    #pragma unroll
    for (int j=0;j<4;j++){ gfr[j][0]=gfr[j][1]=gfr[j][2]=gfr[j][3]=0.f; }
    {
        const float* Ar0 = &Cs[(t0+gr)*132];
        const float* Ar1 = Ar0 + 8*132;
        #pragma unroll
        for (int k0 = 0; k0 < 128; k0 += 8){
            uint32_t a0 = F2U(Ar0[k0+tg]),   a1 = F2U(Ar1[k0+tg]);
            uint32_t a2 = F2U(Ar0[k0+tg+4]), a3 = F2U(Ar1[k0+tg+4]);
            const float* Bk0 = &R0[(k0+tg)*68 + ntb*8 + gr];
            const float* Bk1 = Bk0 + 4*68;
            #pragma unroll
            for (int j=0;j<4;j++)
                mma8(gfr[j], a0,a1,a2,a3, F2U(Bk0[j*8]), F2U(Bk1[j*8]));
        }
    }
    __syncthreads();

    #pragma unroll
    for (int hh=0; hh<NH; hh++){
        float laT0 = la_s[hh*64 + t0+gr];
        float laT1 = la_s[hh*64 + t0+gr+8];
        #pragma unroll
        for (int j=0;j<4;j++){
            int tp0 = (ntb+j)*8 + 2*tg;
            float dtp0 = dt_s[hh*64 + tp0],  dtp1 = dt_s[hh*64 + tp0+1];
            float lap0 = la_s[hh*64 + tp0],  lap1 = la_s[hh*64 + tp0+1];
            int tA = t0+gr, tB = t0+gr+8;
            float w00 = (tp0   <= tA) ? __expf(laT0-lap0)*dtp0*gfr[j][0] : 0.f;
            float w01 = (tp0+1 <= tA) ? __expf(laT0-lap1)*dtp1*gfr[j][1] : 0.f;
            float w10 = (tp0   <= tB) ? __expf(laT1-lap0)*dtp0*gfr[j][2] : 0.f;
            float w11 = (tp0+1 <= tB) ? __expf(laT1-lap1)*dtp1*gfr[j][3] : 0.f;
            Cs[tA*132 + hh*64 + tp0]   = w00;
            Cs[tA*132 + hh*64 + tp0+1] = w01;
            Cs[tB*132 + hh*64 + tp0]   = w10;
            Cs[tB*132 + hh*64 + tp0+1] = w11;
        }
    }
    __syncthreads();

    /* Y GEMM + D*x skip folded in */
    {
        float ya[8][4];
        #pragma unroll
        for (int j=0;j<8;j++){ ya[j][0]=ya[j][1]=ya[j][2]=ya[j][3]=0.f; }
        const float* Wr0 = &Cs[(t0+gr)*132 + h*64];
        const float* Wr1 = Wr0 + 8*132;
        #pragma unroll
        for (int k0 = 0; k0 < 64; k0 += 8){
            uint32_t a0 = F2U(Wr0[k0+tg]),   a1 = F2U(Wr1[k0+tg]);
            uint32_t a2 = F2U(Wr0[k0+tg+4]), a3 = F2U(Wr1[k0+tg+4]);
            const float* Bk0 = &Xs[(k0+tg)*136 + h*64 + gr];
            const float* Bk1 = Bk0 + 4*136;
            #pragma unroll
            for (int j=0;j<8;j++)
                mma8(ya[j], a0,a1,a2,a3, F2U(Bk0[j*8]), F2U(Bk1[j*8]));
        }
        float dh = __ldg(&Dp[h]);
        long row0 = (long)(b*SEQ + l0 + t0 + gr);
        #pragma unroll
        for (int j=0;j<8;j++){
            int col = h*64 + j*8 + 2*tg;
            float2 xa = *(const float2*)&Xs[(t0+gr)*136 + col];
            float2 xb = *(const float2*)&Xs[(t0+gr+8)*136 + col];
            *(float2*)&g_y[row0*DI + col] =
                make_float2(ya[j][0] + dh*xa.x, ya[j][1] + dh*xa.y);
            *(float2*)&g_y[(row0+8)*DI + col] =
                make_float2(ya[j][2] + dh*xb.x, ya[j][3] + dh*xb.y);
        }
    }

    {
        float sa[16][4];
        #pragma unroll
        for (int j=0;j<16;j++){ sa[j][0]=sa[j][1]=sa[j][2]=sa[j][3]=0.f; }
        int pg0 = w*16;
        #pragma unroll
        for (int k0 = 0; k0 < 64; k0 += 8){
            float cfA = cf_s[h*64 + k0+tg];
            float cfB = cf_s[h*64 + k0+tg+4];
            const float* Xk0 = &Xs[(k0+tg)*136 + pg0 + gr];
            const float* Xk1 = Xk0 + 4*136;
            uint32_t a0 = F2U(Xk0[0]*cfA), a1 = F2U(Xk0[8]*cfA);
            uint32_t a2 = F2U(Xk1[0]*cfB), a3 = F2U(Xk1[8]*cfB);
            #pragma unroll
            for (int j=0;j<16;j++){
                const float* Bp = &R0[(j*8+gr)*68 + k0+tg];
                mma8(sa[j], a0,a1,a2,a3, F2U(Bp[0]), F2U(Bp[4]));
            }
        }
        int p = (w&3)*16 + gr;
        long base = (((long)((b*NH+h)*NC + c))*HD)*DS;
        #pragma unroll
        for (int j=0;j<16;j++){
            int s = j*8 + 2*tg;
            *(float2*)&g_S[base + (long)p*DS + s]     = make_float2(sa[j][0], sa[j][1]);
            *(float2*)&g_S[base + (long)(p+8)*DS + s] = make_float2(sa[j][2], sa[j][3]);
        }
    }
}

/* ------ Phase B: inter-chunk recurrence, depth-4 ring, contiguous layout --- */
__global__ void phaseB_kernel(void){
    __shared__ float ea_s[NC];
    int bh   = blockIdx.x >> 4;
    int part = blockIdx.x & 15;
    int tid  = threadIdx.x;           /* 128 threads */
    if (tid < NC) ea_s[tid] = __expf(g_atot[bh*NC + tid]);
    __syncthreads();
    long ebase = (long)bh*NC*(HD*DS) + part*512 + tid*4;
    float4 hv = make_float4(0.f,0.f,0.f,0.f);
    float4 ring[4];
    #pragma unroll
    for (int d=0;d<4;d++) ring[d] = *(const float4*)&g_S[ebase + (long)d*(HD*DS)];
    for (int c = 0; c < NC; c++){
        *(float4*)&g_hst[ebase + (long)c*(HD*DS)] = hv;
        float ea = ea_s[c];
        float4 sv = ring[c & 3];
        hv.x = fmaf(hv.x, ea, sv.x);
        hv.y = fmaf(hv.y, ea, sv.y);
        hv.z = fmaf(hv.z, ea, sv.z);
        hv.w = fmaf(hv.w, ea, sv.w);
        if (c + 4 < NC)
            ring[c & 3] = *(const float4*)&g_S[ebase + (long)(c+4)*(HD*DS)];
    }
}

/* ------ Phase C+G (tf32 mma): inter-chunk out, gate, RMSNorm, out_proj ----- */
/* Hs stored [pg][s] stride 132 (float4 coalesced staging, no transpose);
   GEMM1 B-fragment gathers Hs[n*132 + k] (132%32==4 -> conflict-free).       */
#define SMCG_FLOATS (64*132 + 128*136 + 128)
__global__ void phaseCG_kernel(const float* __restrict__ ow,
                               const float* __restrict__ nw, float* __restrict__ xres){
    int b = blockIdx.x >> 6;
    int c = blockIdx.x & (NC-1);
    int l0 = c*QC;
    extern __shared__ float sm[];
    float* Cs2 = sm;                  /* C [t][s] s132; later owT [k][m] s66 */
    float* Hs  = sm + 64*132;         /* h [pg][s] s132; later yt [t][pg] s136 */
    float* yt  = Hs;
    float* owT = Cs2;
    float* la2 = sm + 64*132 + 128*136;
    int tid = threadIdx.x;

    for (int idx = tid; idx < QC*(DS/4); idx += 256){
        int t = idx >> 5, s4 = (idx & 31)*4;
        *(float4*)&Cs2[t*132 + s4] =
            *(const float4*)&g_c[((long)(b*SEQ+l0+t))*DS + s4];
    }
    for (int idx = tid; idx < DS*DI/4; idx += 256){
        int pg = idx >> 5, s4 = (idx & 31)*4;
        int hh = pg >> 6, p = pg & 63;
        *(float4*)&Hs[pg*132 + s4] =
            *(const float4*)&g_hst[(((long)((b*NH+hh)*NC + c))*HD + p)*DS + s4];
    }
    if (tid < NH*QC){
        int hh = tid >> 6, t = tid & 63;
        la2[tid] = g_lacc[((long)(b*NH+hh))*SEQ + l0 + t];
    }
    __syncthreads();

    int w = tid >> 5, lane = tid & 31, gr = lane >> 2, tg = lane & 3;
    int mt = w & 3, t0 = mt*16, h = w >> 2;
    long row0 = (long)(b*SEQ + l0 + t0 + gr);
    long row1 = row0 + 8;

    /* GEMM1: Yc[t][pg] = sum_s C[t][s]*h[pg][s] */
    float acc[8][4];
    #pragma unroll
    for (int j=0;j<8;j++){ acc[j][0]=acc[j][1]=acc[j][2]=acc[j][3]=0.f; }
    {
        const float* Ar0 = &Cs2[(t0+gr)*132];
        const float* Ar1 = Ar0 + 8*132;
        #pragma unroll
        for (int k0 = 0; k0 < 128; k0 += 8){
            uint32_t a0 = F2U(Ar0[k0+tg]),   a1 = F2U(Ar1[k0+tg]);
            uint32_t a2 = F2U(Ar0[k0+tg+4]), a3 = F2U(Ar1[k0+tg+4]);
            #pragma unroll
            for (int j=0;j<8;j++){
                const float* Bp = &Hs[(h*64 + j*8 + gr)*132 + k0+tg];
                mma8(acc[j], a0,a1,a2,a3, F2U(Bp[0]), F2U(Bp[4]));
            }
        }
    }
    float e0 = __expf(la2[h*64 + t0+gr]);
    float e1 = __expf(la2[h*64 + t0+gr+8]);
    float gated[8][4];
    #pragma unroll
    for (int j=0;j<8;j++){
        int col = h*64 + j*8 + 2*tg;
        float2 y0 = *(const float2*)&g_y[row0*DI + col];
        float2 z0 = *(const float2*)&g_z[row0*DI + col];
        float2 y1 = *(const float2*)&g_y[row1*DI + col];
        float2 z1 = *(const float2*)&g_z[row1*DI + col];
        gated[j][0] = (y0.x + e0*acc[j][0]) * siluf(z0.x);
        gated[j][1] = (y0.y + e0*acc[j][1]) * siluf(z0.y);
        gated[j][2] = (y1.x + e1*acc[j][2]) * siluf(z1.x);
        gated[j][3] = (y1.y + e1*acc[j][3]) * siluf(z1.y);
    }
    __syncthreads();

    #pragma unroll
    for (int j=0;j<8;j++){
        int col = h*64 + j*8 + 2*tg;
        *(float2*)&yt[(t0+gr)*136   + col] = make_float2(gated[j][0], gated[j][1]);
        *(float2*)&yt[(t0+gr+8)*136 + col] = make_float2(gated[j][2], gated[j][3]);
    }
    for (int idx = tid; idx < DM*DI; idx += 256){
        int m = idx >> 7, k = idx & 127;
        owT[k*66 + m] = ow[idx];
    }
    __syncthreads();

    for (int r = w*8; r < w*8 + 8; r++){
        float s = 0.f;
        #pragma unroll
        for (int q=0;q<4;q++){ float v = yt[r*136 + lane + q*32]; s += v*v; }
        #pragma unroll
        for (int o=16;o;o>>=1) s += __shfl_xor_sync(0xffffffffu, s, o);
        float rstd = rsqrtf(s/(float)DI + EPSV);
        #pragma unroll
        for (int q=0;q<4;q++){
            int cc = lane + q*32;
            yt[r*136 + cc] *= rstd * __ldg(&nw[cc]);
        }
    }
    __syncthreads();

    {
        float oacc[4][4];
        #pragma unroll
        for (int j=0;j<4;j++){ oacc[j][0]=oacc[j][1]=oacc[j][2]=oacc[j][3]=0.f; }
        int ntb = (w >> 2)*4;
        const float* Ar0 = &yt[(t0+gr)*136];
        const float* Ar1 = Ar0 + 8*136;
        #pragma unroll
        for (int k0 = 0; k0 < 128; k0 += 8){
            uint32_t a0 = F2U(Ar0[k0+tg]),   a1 = F2U(Ar1[k0+tg]);
            uint32_t a2 = F2U(Ar0[k0+tg+4]), a3 = F2U(Ar1[k0+tg+4]);
            const float* Bk0 = &owT[(k0+tg)*66 + ntb*8 + gr];
            const float* Bk1 = Bk0 + 4*66;
            #pragma unroll
            for (int j=0;j<4;j++)
                mma8(oacc[j], a0,a1,a2,a3, F2U(Bk0[j*8]), F2U(Bk1[j*8]));
        }
        #pragma unroll
        for (int j=0;j<4;j++){
            int col = (ntb+j)*8 + 2*tg;
            float2 o0 = *(float2*)&xres[row0*DM + col];
            o0.x += oacc[j][0]; o0.y += oacc[j][1];
            *(float2*)&xres[row0*DM + col] = o0;
            float2 o1 = *(float2*)&xres[row1*DM + col];
            o1.x += oacc[j][2]; o1.y += oacc[j][3];
            *(float2*)&xres[row1*DM + col] = o1;
        }
    }
}

/* ---------------- host ----------------------------------------------------- */
extern "C" void kernel_launch(void* const* d_in, const int* in_sizes, int n_in,
                              void* d_out, int out_size){
    const float* x0    = (const float*)d_in[0];
    const float* inw   = (const float*)d_in[1];
    const float* cw    = (const float*)d_in[2];
    const float* cb    = (const float*)d_in[3];
    const float* dtb   = (const float*)d_in[4];
    const float* alog  = (const float*)d_in[5];
    const float* Dpar  = (const float*)d_in[6];
    const float* nw    = (const float*)d_in[7];
    const float* ow    = (const float*)d_in[8];
    float* out = (float*)d_out;

    cudaFuncSetAttribute(phaseA_kernel,  cudaFuncAttributeMaxDynamicSharedMemorySize, SMA_FLOATS*4);
    cudaFuncSetAttribute(phaseCG_kernel, cudaFuncAttributeMaxDynamicSharedMemorySize, SMCG_FLOATS*4);

    copy_kernel<<<(BL*DM/4+255)/256, 256>>>(x0, out, BL*DM/4);

    const int DPROJ = DZX + NH;
    for (int layer = 0; layer < NLAYERS; layer++){
        const float* Wl = inw + (long)layer*DPROJ*DM;
        inproj_kernel<<<dim3(BL/128, DZX/128), 256>>>(out, Wl);
        phaseA_kernel<<<BSZ*NC, 256, SMA_FLOATS*4>>>(out, Wl, dtb + layer*NH, alog + layer*NH,
                                                     cw + (long)layer*CONVD*DCONV,
                                                     cb + layer*CONVD,
                                                     Dpar + layer*NH);
        phaseB_kernel<<<BSZ*NH*16, 128>>>();
        phaseCG_kernel<<<BSZ*NC, 256, SMCG_FLOATS*4>>>(ow + (long)layer*DM*DI,
                                                       nw + layer*DI, out);
    }
    (void)in_sizes; (void)n_in; (void)out_size;
}